// round 15
// baseline (speedup 1.0000x reference)
#include <cuda_runtime.h>
#include <cuda_fp16.h>
#include <cstdint>

#define HID 1024
#define MROWS 32768
#define STAGE 16384
#define DSMEM_TOTAL (4 * STAGE)

// ---- static device scratch (allocation-free rule) ----
__device__ __align__(16) __half g_x16 [(size_t)MROWS * 512];
__device__ __align__(16) __half g_w16 [(size_t)3 * HID * 512];
__device__ __align__(16) __half g_WH16[(size_t)5 * HID * HID];
__device__ __align__(16) __half g_WT16[(size_t)5 * HID * HID];
__device__ __align__(16) __half g_WC16[(size_t)5 * HID * HID];
__device__ __align__(16) __half g_h16A[(size_t)MROWS * HID];
__device__ __align__(16) __half g_h16B[(size_t)MROWS * HID];

// ---- helpers ----
__device__ __forceinline__ uint32_t smem_u32(const void* p) {
    uint32_t a;
    asm("{ .reg .u64 t; cvta.to.shared.u64 t, %1; cvt.u32.u64 %0, t; }" : "=r"(a) : "l"(p));
    return a;
}
__device__ __forceinline__ void cpa16(uint32_t s, const void* g) {
    asm volatile("cp.async.cg.shared.global [%0], [%1], 16;" :: "r"(s), "l"(g));
}
__device__ __forceinline__ void cpa_commit() {
    asm volatile("cp.async.commit_group;" ::: "memory");
}
__device__ __forceinline__ void cpa_wait2() {
    asm volatile("cp.async.wait_group 2;" ::: "memory");
}
__device__ __forceinline__ void ldsm4(uint32_t* r, uint32_t a) {
    asm volatile("ldmatrix.sync.aligned.m8n8.x4.shared.b16 {%0,%1,%2,%3}, [%4];"
                 : "=r"(r[0]), "=r"(r[1]), "=r"(r[2]), "=r"(r[3]) : "r"(a));
}
__device__ __forceinline__ void mma16816(float* d, const uint32_t* a, uint32_t b0, uint32_t b1) {
    asm volatile(
        "mma.sync.aligned.m16n8k16.row.col.f32.f16.f16.f32 "
        "{%0,%1,%2,%3}, {%4,%5,%6,%7}, {%8,%9}, {%0,%1,%2,%3};"
        : "+f"(d[0]), "+f"(d[1]), "+f"(d[2]), "+f"(d[3])
        : "r"(a[0]), "r"(a[1]), "r"(a[2]), "r"(a[3]), "r"(b0), "r"(b1));
}
// swizzled byte offset of a 16B chunk (row r, chunk c in 0..3) of a k32 fp16 tile
__device__ __forceinline__ uint32_t swz32(int r, int c) {
    return (uint32_t)((r >> 1) * 128 + (r & 1) * 64 + ((c ^ ((r >> 1) & 3)) << 4));
}
__device__ __forceinline__ float sigm_(float x) { return __fdividef(1.f, 1.f + __expf(-x)); }
__device__ __forceinline__ float tanh_(float x) {
    float ax = fabsf(x), e = __expf(-2.f * ax);
    float t = __fdividef(1.f - e, 1.f + e);
    return x >= 0.f ? t : -t;
}
__device__ __forceinline__ uint32_t f2h(float f) {
    return (uint32_t)__half_as_ushort(__float2half_rn(f));
}
__device__ __forceinline__ float h2f_lo(uint32_t u) {
    return __half2float(__ushort_as_half((unsigned short)(u & 0xFFFFu)));
}
__device__ __forceinline__ float h2f_hi(uint32_t u) {
    return __half2float(__ushort_as_half((unsigned short)(u >> 16)));
}

// ---- fp32 -> fp16 convert ----
__global__ void cvt4(const float4* __restrict__ src, uint2* __restrict__ dst, int n4) {
    int i = blockIdx.x * blockDim.x + threadIdx.x;
    if (i >= n4) return;
    float4 v = src[i];
    uint2 o;
    o.x = f2h(v.x) | (f2h(v.y) << 16);
    o.y = f2h(v.z) | (f2h(v.w) << 16);
    dst[i] = o;
}
__global__ void cvt4w(const float4* __restrict__ s0, uint2* __restrict__ d0,
                      const float4* __restrict__ s1, uint2* __restrict__ d1,
                      const float4* __restrict__ s2, uint2* __restrict__ d2, int n4) {
    int i = blockIdx.x * blockDim.x + threadIdx.x;
    if (i >= n4) return;
    const float4* src = blockIdx.z == 0 ? s0 : (blockIdx.z == 1 ? s1 : s2);
    uint2* dst = blockIdx.z == 0 ? d0 : (blockIdx.z == 1 ? d1 : d2);
    float4 v = src[i];
    uint2 o;
    o.x = f2h(v.x) | (f2h(v.y) << 16);
    o.y = f2h(v.z) | (f2h(v.w) << 16);
    dst[i] = o;
}

// ---- fused 3-gate fp16 mma.sync GEMM + epilogue ----
// CTA tile M=64, N=64 per gate, 3 gates. 128 threads, 4 warps (warp = 16-col n-group,
// covers all 64 M-rows). B LDSM redundancy 1, A redundancy 4. 3 CTAs/SM.
// k32 chunks, 4-stage pipeline, ONE __syncthreads per chunk, issue BEFORE compute.
// smem stage (16KB): A[0,4K) 64x(k32); Bg at 4K*(1+g).
template<int KF, int MODE, int WRH>
__global__ void __launch_bounds__(128, 3)
rhn_h(const __half* __restrict__ Ah,
      const __half* __restrict__ B0, const __half* __restrict__ B1, const __half* __restrict__ B2,
      const float* __restrict__ e0, const float* __restrict__ e1, const float* __restrict__ e2,
      const __half* __restrict__ hin,
      float* __restrict__ outF, __half* __restrict__ outH)
{
    constexpr int NK = KF / 32;
    extern __shared__ __align__(128) uint8_t smemraw[];
    const uint32_t sbase = smem_u32(smemraw);

    const int tid = threadIdx.x;
    const int lane = tid & 31;
    const int w = tid >> 5;
    const int m0 = blockIdx.y * 64;
    const int n0 = blockIdx.x * 64;

    // ---- producer mapping: 8 x cpa16 per thread per stage (2 A + 6 B) ----
    const int pr = tid >> 1;            // 0..63
    const int pcb = (tid & 1) * 2;      // chunk base 0 or 2
    const char* gA = (const char*)(Ah + (size_t)(m0 + pr) * KF + pcb * 8);
    const char* gB[3];
    {
        const __half* bp[3] = {B0, B1, B2};
#pragma unroll
        for (int g = 0; g < 3; g++)
            gB[g] = (const char*)(bp[g] + (size_t)(n0 + pr) * KF + pcb * 8);
    }
    uint32_t soA[2], soB[3][2];
#pragma unroll
    for (int j = 0; j < 2; j++) {
        soA[j] = swz32(pr, pcb + j);
#pragma unroll
        for (int g = 0; g < 3; g++)
            soB[g][j] = 4096u * (1 + g) + swz32(pr, pcb + j);
    }

    // ---- consumer: fully precomputed ldmatrix offsets ----
    const int mat = lane >> 3;
    const int khf = lane >> 4;
    const int swl = lane & 7;
    uint32_t aoff[4][2], boff[2];
#pragma unroll
    for (int mi = 0; mi < 4; mi++) {
        int r = mi * 16 + (mat & 1) * 8 + swl;
        uint32_t base = (uint32_t)((r >> 1) * 128 + (r & 1) * 64);
        int sw = (r >> 1) & 3;
#pragma unroll
        for (int ks = 0; ks < 2; ks++)
            aoff[mi][ks] = base + (uint32_t)(((ks * 2 + khf) ^ sw) << 4);
    }
    {
        int r = w * 16 + (mat & 1) * 8 + swl;
        uint32_t base = 4096u + (uint32_t)((r >> 1) * 128 + (r & 1) * 64);
        int sw = (r >> 1) & 3;
#pragma unroll
        for (int ks = 0; ks < 2; ks++)
            boff[ks] = base + (uint32_t)(((ks * 2 + khf) ^ sw) << 4);
    }

    float acc[3][4][2][4];
#pragma unroll
    for (int g = 0; g < 3; g++)
#pragma unroll
        for (int mi = 0; mi < 4; mi++)
#pragma unroll
            for (int nf = 0; nf < 2; nf++)
#pragma unroll
                for (int e = 0; e < 4; e++) acc[g][mi][nf][e] = 0.f;

#define ISSUE_TO(SB)                                                          \
    {                                                                         \
        cpa16((SB) + soA[0], gA);                                             \
        cpa16((SB) + soA[1], gA + 16);                                        \
        _Pragma("unroll")                                                     \
        for (int g = 0; g < 3; g++) {                                         \
            cpa16((SB) + soB[g][0], gB[g]);                                   \
            cpa16((SB) + soB[g][1], gB[g] + 16);                              \
        }                                                                     \
    }
#define ADV()                                                                 \
    { gA += 64; gB[0] += 64; gB[1] += 64; gB[2] += 64; }

    // preload chunks 0..2 into slots 0..2
#pragma unroll
    for (int s = 0; s < 3; s++) {
        ISSUE_TO(sbase + s * STAGE); cpa_commit(); ADV();
    }

    uint32_t rd = sbase;
    uint32_t wr = sbase + 3u * STAGE;
    const uint32_t send = sbase + 4u * STAGE;

    for (int i = 0; i < NK; i++) {
        cpa_wait2();        // chunk i landed (i+1, i+2 may be in flight)
        __syncthreads();    // all warps done with chunk i-1 -> slot (i+3)&3 free

        if (i + 3 < NK) { ISSUE_TO(wr); ADV(); }
        cpa_commit();

#pragma unroll
        for (int ks = 0; ks < 2; ks++) {
            uint32_t a4[16], b4[12];
#pragma unroll
            for (int mi = 0; mi < 4; mi++)
                ldsm4(a4 + mi * 4, rd + aoff[mi][ks]);
            uint32_t bb = rd + boff[ks];
            ldsm4(b4, bb);
            ldsm4(b4 + 4, bb + 4096u);
            ldsm4(b4 + 8, bb + 8192u);
#pragma unroll
            for (int g = 0; g < 3; g++)
#pragma unroll
                for (int mi = 0; mi < 4; mi++) {
                    mma16816(acc[g][mi][0], a4 + mi * 4, b4[g * 4 + 0], b4[g * 4 + 2]);
                    mma16816(acc[g][mi][1], a4 + mi * 4, b4[g * 4 + 1], b4[g * 4 + 3]);
                }
        }
        rd += STAGE; if (rd == send) rd = sbase;
        wr += STAGE; if (wr == send) wr = sbase;
    }

    // ---- epilogue ----
    float bA[2][2], bB[2][2], bC2[2][2], bD[2][2];
#pragma unroll
    for (int nf = 0; nf < 2; nf++) {
        int n = n0 + w * 16 + nf * 8 + (lane & 3) * 2;
        if (MODE == 0) {
            float2 i0 = *(const float2*)&e0[n],         h0 = *(const float2*)&e1[n];
            float2 i1 = *(const float2*)&e0[HID + n],   h1 = *(const float2*)&e1[HID + n];
            float2 i2 = *(const float2*)&e0[2*HID + n], h2 = *(const float2*)&e1[2*HID + n];
            bA[nf][0] = i0.x + h0.x; bA[nf][1] = i0.y + h0.y;
            bB[nf][0] = i1.x + h1.x; bB[nf][1] = i1.y + h1.y;
            bC2[nf][0] = i2.x;       bC2[nf][1] = i2.y;
            bD[nf][0] = h2.x;        bD[nf][1] = h2.y;
        } else {
            float2 v0 = *(const float2*)&e0[n];
            float2 v1 = *(const float2*)&e1[n];
            float2 v2 = *(const float2*)&e2[n];
            bA[nf][0] = v0.x; bA[nf][1] = v0.y;
            bB[nf][0] = v1.x; bB[nf][1] = v1.y;
            bC2[nf][0] = v2.x; bC2[nf][1] = v2.y;
        }
    }

#pragma unroll
    for (int mi = 0; mi < 4; mi++) {
#pragma unroll
        for (int half = 0; half < 2; half++) {
            const int m = m0 + mi * 16 + (lane >> 2) + half * 8;
#pragma unroll
            for (int nf = 0; nf < 2; nf++) {
                const int n = n0 + w * 16 + nf * 8 + (lane & 3) * 2;
                float res[2];
                float hv0 = 0.f, hv1 = 0.f;
                if (MODE == 1) {
                    uint32_t hw = *(const uint32_t*)(hin + (size_t)m * HID + n);
                    hv0 = h2f_lo(hw); hv1 = h2f_hi(hw);
                }
#pragma unroll
                for (int e = 0; e < 2; e++) {
                    float a0 = acc[0][mi][nf][half * 2 + e];
                    float a1 = acc[1][mi][nf][half * 2 + e];
                    float a2 = acc[2][mi][nf][half * 2 + e];
                    if (MODE == 0) {
                        float r = sigm_(a0 + bA[nf][e]);
                        float z = sigm_(a1 + bB[nf][e]);
                        float nn = tanh_(a2 + bC2[nf][e] + r * bD[nf][e]);
                        res[e] = (1.f - z) * nn;
                    } else {
                        float hh = tanh_(a0 + bA[nf][e]);
                        float t  = sigm_(a1 + bB[nf][e]);
                        float cc = sigm_(a2 + bC2[nf][e]);
                        float hi = (e == 0) ? hv0 : hv1;
                        res[e] = hh * t + hi * (1.f - cc);
                    }
                }
                if (WRH) {
                    *(uint32_t*)(outH + (size_t)m * HID + n) = f2h(res[0]) | (f2h(res[1]) << 16);
                } else {
                    *(float2*)(outF + (size_t)m * HID + n) = make_float2(res[0], res[1]);
                }
            }
        }
    }
}

extern "C" void kernel_launch(void* const* d_in, const int* in_sizes, int n_in,
                              void* d_out, int out_size)
{
    const float* x    = (const float*)d_in[0];
    const float* w_ih = (const float*)d_in[1];
    const float* b_ih = (const float*)d_in[3];
    const float* b_hh = (const float*)d_in[4];
    const float* WH   = (const float*)d_in[5];
    const float* bH   = (const float*)d_in[6];
    const float* WT   = (const float*)d_in[7];
    const float* bT   = (const float*)d_in[8];
    const float* WC   = (const float*)d_in[9];
    const float* bC   = (const float*)d_in[10];
    float* out = (float*)d_out;

    static bool attrSet = false;
    if (!attrSet) {
        cudaFuncSetAttribute(rhn_h<512, 0, 1>,  cudaFuncAttributeMaxDynamicSharedMemorySize, DSMEM_TOTAL);
        cudaFuncSetAttribute(rhn_h<1024, 1, 1>, cudaFuncAttributeMaxDynamicSharedMemorySize, DSMEM_TOTAL);
        cudaFuncSetAttribute(rhn_h<1024, 1, 0>, cudaFuncAttributeMaxDynamicSharedMemorySize, DSMEM_TOTAL);
        attrSet = true;
    }

    __half *x16, *w16, *WH16, *WT16, *WC16, *h16A, *h16B;
    cudaGetSymbolAddress((void**)&x16, g_x16);
    cudaGetSymbolAddress((void**)&w16, g_w16);
    cudaGetSymbolAddress((void**)&WH16, g_WH16);
    cudaGetSymbolAddress((void**)&WT16, g_WT16);
    cudaGetSymbolAddress((void**)&WC16, g_WC16);
    cudaGetSymbolAddress((void**)&h16A, g_h16A);
    cudaGetSymbolAddress((void**)&h16B, g_h16B);

    {
        int n4 = MROWS * 512 / 4;
        cvt4<<<(n4 + 255) / 256, 256>>>((const float4*)x, (uint2*)x16, n4);
        n4 = 3 * HID * 512 / 4;
        cvt4<<<(n4 + 255) / 256, 256>>>((const float4*)w_ih, (uint2*)w16, n4);
        n4 = 5 * HID * HID / 4;
        dim3 g((n4 + 255) / 256, 1, 3);
        cvt4w<<<g, 256>>>((const float4*)WH, (uint2*)WH16,
                          (const float4*)WT, (uint2*)WT16,
                          (const float4*)WC, (uint2*)WC16, n4);
    }

    dim3 grd(HID / 64, MROWS / 64);
    rhn_h<512, 0, 1><<<grd, 128, DSMEM_TOTAL>>>(
        x16,
        w16, w16 + (size_t)HID * 512, w16 + (size_t)2 * HID * 512,
        b_ih, b_hh, nullptr,
        nullptr, nullptr, h16A);

    for (int s = 0; s < 5; s++) {
        size_t wo = (size_t)s * HID * HID;
        const __half* ih = (s & 1) ? h16B : h16A;
        __half* oh = (s & 1) ? h16A : h16B;
        if (s == 4)
            rhn_h<1024, 1, 0><<<grd, 128, DSMEM_TOTAL>>>(
                ih, WH16 + wo, WT16 + wo, WC16 + wo,
                bH + s * HID, bT + s * HID, bC + s * HID,
                ih, out, nullptr);
        else
            rhn_h<1024, 1, 1><<<grd, 128, DSMEM_TOTAL>>>(
                ih, WH16 + wo, WT16 + wo, WC16 + wo,
                bH + s * HID, bT + s * HID, bC + s * HID,
                ih, nullptr, oh);
    }
}

// round 16
// speedup vs baseline: 1.3327x; 1.3327x over previous
#include <cuda_runtime.h>
#include <cuda_fp16.h>
#include <cstdint>

#define HID 1024
#define MROWS 32768
#define STAGE 32768
#define DSMEM_TOTAL (2 * STAGE)

// ---- static device scratch (allocation-free rule) ----
__device__ __align__(16) __half g_x16 [(size_t)MROWS * 512];
__device__ __align__(16) __half g_w16 [(size_t)3 * HID * 512];
__device__ __align__(16) __half g_WH16[(size_t)5 * HID * HID];
__device__ __align__(16) __half g_WT16[(size_t)5 * HID * HID];
__device__ __align__(16) __half g_WC16[(size_t)5 * HID * HID];
__device__ __align__(16) __half g_h16A[(size_t)MROWS * HID];
__device__ __align__(16) __half g_h16B[(size_t)MROWS * HID];

// ---- helpers ----
__device__ __forceinline__ uint32_t smem_u32(const void* p) {
    uint32_t a;
    asm("{ .reg .u64 t; cvta.to.shared.u64 t, %1; cvt.u32.u64 %0, t; }" : "=r"(a) : "l"(p));
    return a;
}
__device__ __forceinline__ void cpa16(uint32_t s, const void* g) {
    asm volatile("cp.async.cg.shared.global [%0], [%1], 16;" :: "r"(s), "l"(g));
}
// L1-allocating variant: A tiles are shared by the 3 co-resident CTAs (same m0).
__device__ __forceinline__ void cpa16_ca(uint32_t s, const void* g) {
    asm volatile("cp.async.ca.shared.global [%0], [%1], 16;" :: "r"(s), "l"(g));
}
__device__ __forceinline__ void cpa_commit() {
    asm volatile("cp.async.commit_group;" ::: "memory");
}
__device__ __forceinline__ void cpa_wait1() {
    asm volatile("cp.async.wait_group 1;" ::: "memory");
}
__device__ __forceinline__ void ldsm4(uint32_t* r, uint32_t a) {
    asm volatile("ldmatrix.sync.aligned.m8n8.x4.shared.b16 {%0,%1,%2,%3}, [%4];"
                 : "=r"(r[0]), "=r"(r[1]), "=r"(r[2]), "=r"(r[3]) : "r"(a));
}
__device__ __forceinline__ void mma16816(float* d, const uint32_t* a, uint32_t b0, uint32_t b1) {
    asm volatile(
        "mma.sync.aligned.m16n8k16.row.col.f32.f16.f16.f32 "
        "{%0,%1,%2,%3}, {%4,%5,%6,%7}, {%8,%9}, {%0,%1,%2,%3};"
        : "+f"(d[0]), "+f"(d[1]), "+f"(d[2]), "+f"(d[3])
        : "r"(a[0]), "r"(a[1]), "r"(a[2]), "r"(a[3]), "r"(b0), "r"(b1));
}
// swizzled byte offset inside a k64 (128B-row) fp16 tile: row r, 16B chunk c (0..7)
__device__ __forceinline__ uint32_t swz64(int r, int c) {
    return (uint32_t)(r * 128 + ((c ^ (r & 7)) << 4));
}
__device__ __forceinline__ float sigm_(float x) { return __fdividef(1.f, 1.f + __expf(-x)); }
__device__ __forceinline__ float tanh_(float x) {
    float ax = fabsf(x), e = __expf(-2.f * ax);
    float t = __fdividef(1.f - e, 1.f + e);
    return x >= 0.f ? t : -t;
}
__device__ __forceinline__ uint32_t f2h(float f) {
    return (uint32_t)__half_as_ushort(__float2half_rn(f));
}
__device__ __forceinline__ float h2f_lo(uint32_t u) {
    return __half2float(__ushort_as_half((unsigned short)(u & 0xFFFFu)));
}
__device__ __forceinline__ float h2f_hi(uint32_t u) {
    return __half2float(__ushort_as_half((unsigned short)(u >> 16)));
}

// ---- fp32 -> fp16 convert ----
__global__ void cvt4(const float4* __restrict__ src, uint2* __restrict__ dst, int n4) {
    int i = blockIdx.x * blockDim.x + threadIdx.x;
    if (i >= n4) return;
    float4 v = src[i];
    uint2 o;
    o.x = f2h(v.x) | (f2h(v.y) << 16);
    o.y = f2h(v.z) | (f2h(v.w) << 16);
    dst[i] = o;
}
__global__ void cvt4w(const float4* __restrict__ s0, uint2* __restrict__ d0,
                      const float4* __restrict__ s1, uint2* __restrict__ d1,
                      const float4* __restrict__ s2, uint2* __restrict__ d2, int n4) {
    int i = blockIdx.x * blockDim.x + threadIdx.x;
    if (i >= n4) return;
    const float4* src = blockIdx.z == 0 ? s0 : (blockIdx.z == 1 ? s1 : s2);
    uint2* dst = blockIdx.z == 0 ? d0 : (blockIdx.z == 1 ? d1 : d2);
    float4 v = src[i];
    uint2 o;
    o.x = f2h(v.x) | (f2h(v.y) << 16);
    o.y = f2h(v.z) | (f2h(v.w) << 16);
    dst[i] = o;
}

// ---- fused 3-gate fp16 mma.sync GEMM + epilogue ----
// CTA tile M=64, N=64 per gate, 3 gates. 128 threads, 4 warps (warp = 16-col n-group,
// covers all 64 M-rows). B LDSM redundancy 1, A redundancy 4. 3 CTAs/SM.
// k64 chunks, 2-stage double buffer. smem stage: A[0,8K); Bg at 8K+g*8K.
template<int KF, int MODE, int WRH>
__global__ void __launch_bounds__(128, 3)
rhn_h(const __half* __restrict__ Ah,
      const __half* __restrict__ B0, const __half* __restrict__ B1, const __half* __restrict__ B2,
      const float* __restrict__ e0, const float* __restrict__ e1, const float* __restrict__ e2,
      const __half* __restrict__ hin,
      float* __restrict__ outF, __half* __restrict__ outH)
{
    constexpr int NK = KF / 64;
    constexpr int JSTRIDE = 16 * KF * 2;   // 16 rows in bytes
    extern __shared__ __align__(128) uint8_t smemraw[];
    const uint32_t sbase = smem_u32(smemraw);

    const int tid = threadIdx.x;
    const int lane = tid & 31;
    const int w = tid >> 5;
    const int m0 = blockIdx.y * 64;
    const int n0 = blockIdx.x * 64;

    // ---- producer mapping: 16 x cpa16 per thread per stage ----
    const int br = tid >> 3;
    const int pc = tid & 7;
    const char* gA = (const char*)(Ah + (size_t)(m0 + br) * KF + pc * 8);
    const char* gB[3];
    {
        const __half* bp[3] = {B0, B1, B2};
#pragma unroll
        for (int g = 0; g < 3; g++)
            gB[g] = (const char*)(bp[g] + (size_t)(n0 + br) * KF + pc * 8);
    }
    const uint32_t soA = swz64(br, pc);

    // ---- consumer bases ----
    const int mat = lane >> 3;
    const int khf = lane >> 4;
    const int swl = lane & 7;
    uint32_t aoffb[4];
#pragma unroll
    for (int mi = 0; mi < 4; mi++)
        aoffb[mi] = (uint32_t)((mi * 16 + (mat & 1) * 8 + swl) * 128);
    const uint32_t boffb = 8192u + (uint32_t)((w * 16 + (mat & 1) * 8 + swl) * 128);
    uint32_t cidx[4];
#pragma unroll
    for (int ks = 0; ks < 4; ks++)
        cidx[ks] = (uint32_t)(((ks * 2 + khf) ^ swl) << 4);

    float acc[3][4][2][4];
#pragma unroll
    for (int g = 0; g < 3; g++)
#pragma unroll
        for (int mi = 0; mi < 4; mi++)
#pragma unroll
            for (int nf = 0; nf < 2; nf++)
#pragma unroll
                for (int e = 0; e < 4; e++) acc[g][mi][nf][e] = 0.f;

#define ISSUE_TO(SB)                                                          \
    {                                                                         \
        _Pragma("unroll")                                                     \
        for (int j = 0; j < 4; j++) {                                         \
            cpa16_ca((SB) + soA + j * 2048u, gA + (size_t)j * JSTRIDE);       \
            _Pragma("unroll")                                                 \
            for (int g = 0; g < 3; g++)                                       \
                cpa16((SB) + soA + 8192u + g * 8192u + j * 2048u,             \
                      gB[g] + (size_t)j * JSTRIDE);                           \
        }                                                                     \
    }
#define ADV()                                                                 \
    { gA += 128; gB[0] += 128; gB[1] += 128; gB[2] += 128; }

    // preload chunks 0,1 into slots 0,1
    ISSUE_TO(sbase); cpa_commit(); ADV();
    ISSUE_TO(sbase + STAGE); cpa_commit(); ADV();

    uint32_t rd = sbase;

    for (int i = 0; i < NK; i++) {
        cpa_wait1();
        __syncthreads();

#pragma unroll
        for (int ks = 0; ks < 4; ks++) {
            uint32_t a4[16], b4[12];
#pragma unroll
            for (int mi = 0; mi < 4; mi++)
                ldsm4(a4 + mi * 4, rd + aoffb[mi] + cidx[ks]);
            uint32_t bb = rd + boffb + cidx[ks];
            ldsm4(b4, bb);
            ldsm4(b4 + 4, bb + 8192u);
            ldsm4(b4 + 8, bb + 16384u);
#pragma unroll
            for (int g = 0; g < 3; g++)
#pragma unroll
                for (int mi = 0; mi < 4; mi++) {
                    mma16816(acc[g][mi][0], a4 + mi * 4, b4[g * 4 + 0], b4[g * 4 + 2]);
                    mma16816(acc[g][mi][1], a4 + mi * 4, b4[g * 4 + 1], b4[g * 4 + 3]);
                }
        }
        __syncthreads();

        if (i + 2 < NK) { ISSUE_TO(rd); ADV(); }
        cpa_commit();
        rd ^= STAGE;
    }

    // ---- epilogue ----
    float bA[2][2], bB[2][2], bC2[2][2], bD[2][2];
#pragma unroll
    for (int nf = 0; nf < 2; nf++) {
        int n = n0 + w * 16 + nf * 8 + (lane & 3) * 2;
        if (MODE == 0) {
            float2 i0 = *(const float2*)&e0[n],         h0 = *(const float2*)&e1[n];
            float2 i1 = *(const float2*)&e0[HID + n],   h1 = *(const float2*)&e1[HID + n];
            float2 i2 = *(const float2*)&e0[2*HID + n], h2 = *(const float2*)&e1[2*HID + n];
            bA[nf][0] = i0.x + h0.x; bA[nf][1] = i0.y + h0.y;
            bB[nf][0] = i1.x + h1.x; bB[nf][1] = i1.y + h1.y;
            bC2[nf][0] = i2.x;       bC2[nf][1] = i2.y;
            bD[nf][0] = h2.x;        bD[nf][1] = h2.y;
        } else {
            float2 v0 = *(const float2*)&e0[n];
            float2 v1 = *(const float2*)&e1[n];
            float2 v2 = *(const float2*)&e2[n];
            bA[nf][0] = v0.x; bA[nf][1] = v0.y;
            bB[nf][0] = v1.x; bB[nf][1] = v1.y;
            bC2[nf][0] = v2.x; bC2[nf][1] = v2.y;
        }
    }

#pragma unroll
    for (int mi = 0; mi < 4; mi++) {
#pragma unroll
        for (int half = 0; half < 2; half++) {
            const int m = m0 + mi * 16 + (lane >> 2) + half * 8;
#pragma unroll
            for (int nf = 0; nf < 2; nf++) {
                const int n = n0 + w * 16 + nf * 8 + (lane & 3) * 2;
                float res[2];
                float hv0 = 0.f, hv1 = 0.f;
                if (MODE == 1) {
                    uint32_t hw = *(const uint32_t*)(hin + (size_t)m * HID + n);
                    hv0 = h2f_lo(hw); hv1 = h2f_hi(hw);
                }
#pragma unroll
                for (int e = 0; e < 2; e++) {
                    float a0 = acc[0][mi][nf][half * 2 + e];
                    float a1 = acc[1][mi][nf][half * 2 + e];
                    float a2 = acc[2][mi][nf][half * 2 + e];
                    if (MODE == 0) {
                        float r = sigm_(a0 + bA[nf][e]);
                        float z = sigm_(a1 + bB[nf][e]);
                        float nn = tanh_(a2 + bC2[nf][e] + r * bD[nf][e]);
                        res[e] = (1.f - z) * nn;
                    } else {
                        float hh = tanh_(a0 + bA[nf][e]);
                        float t  = sigm_(a1 + bB[nf][e]);
                        float cc = sigm_(a2 + bC2[nf][e]);
                        float hi = (e == 0) ? hv0 : hv1;
                        res[e] = hh * t + hi * (1.f - cc);
                    }
                }
                if (WRH) {
                    *(uint32_t*)(outH + (size_t)m * HID + n) = f2h(res[0]) | (f2h(res[1]) << 16);
                } else {
                    *(float2*)(outF + (size_t)m * HID + n) = make_float2(res[0], res[1]);
                }
            }
        }
    }
}

extern "C" void kernel_launch(void* const* d_in, const int* in_sizes, int n_in,
                              void* d_out, int out_size)
{
    const float* x    = (const float*)d_in[0];
    const float* w_ih = (const float*)d_in[1];
    const float* b_ih = (const float*)d_in[3];
    const float* b_hh = (const float*)d_in[4];
    const float* WH   = (const float*)d_in[5];
    const float* bH   = (const float*)d_in[6];
    const float* WT   = (const float*)d_in[7];
    const float* bT   = (const float*)d_in[8];
    const float* WC   = (const float*)d_in[9];
    const float* bC   = (const float*)d_in[10];
    float* out = (float*)d_out;

    static bool attrSet = false;
    if (!attrSet) {
        cudaFuncSetAttribute(rhn_h<512, 0, 1>,  cudaFuncAttributeMaxDynamicSharedMemorySize, DSMEM_TOTAL);
        cudaFuncSetAttribute(rhn_h<1024, 1, 1>, cudaFuncAttributeMaxDynamicSharedMemorySize, DSMEM_TOTAL);
        cudaFuncSetAttribute(rhn_h<1024, 1, 0>, cudaFuncAttributeMaxDynamicSharedMemorySize, DSMEM_TOTAL);
        attrSet = true;
    }

    __half *x16, *w16, *WH16, *WT16, *WC16, *h16A, *h16B;
    cudaGetSymbolAddress((void**)&x16, g_x16);
    cudaGetSymbolAddress((void**)&w16, g_w16);
    cudaGetSymbolAddress((void**)&WH16, g_WH16);
    cudaGetSymbolAddress((void**)&WT16, g_WT16);
    cudaGetSymbolAddress((void**)&WC16, g_WC16);
    cudaGetSymbolAddress((void**)&h16A, g_h16A);
    cudaGetSymbolAddress((void**)&h16B, g_h16B);

    {
        int n4 = MROWS * 512 / 4;
        cvt4<<<(n4 + 255) / 256, 256>>>((const float4*)x, (uint2*)x16, n4);
        n4 = 3 * HID * 512 / 4;
        cvt4<<<(n4 + 255) / 256, 256>>>((const float4*)w_ih, (uint2*)w16, n4);
        n4 = 5 * HID * HID / 4;
        dim3 g((n4 + 255) / 256, 1, 3);
        cvt4w<<<g, 256>>>((const float4*)WH, (uint2*)WH16,
                          (const float4*)WT, (uint2*)WT16,
                          (const float4*)WC, (uint2*)WC16, n4);
    }

    dim3 grd(HID / 64, MROWS / 64);
    rhn_h<512, 0, 1><<<grd, 128, DSMEM_TOTAL>>>(
        x16,
        w16, w16 + (size_t)HID * 512, w16 + (size_t)2 * HID * 512,
        b_ih, b_hh, nullptr,
        nullptr, nullptr, h16A);

    for (int s = 0; s < 5; s++) {
        size_t wo = (size_t)s * HID * HID;
        const __half* ih = (s & 1) ? h16B : h16A;
        __half* oh = (s & 1) ? h16A : h16B;
        if (s == 4)
            rhn_h<1024, 1, 0><<<grd, 128, DSMEM_TOTAL>>>(
                ih, WH16 + wo, WT16 + wo, WC16 + wo,
                bH + s * HID, bT + s * HID, bC + s * HID,
                ih, out, nullptr);
        else
            rhn_h<1024, 1, 1><<<grd, 128, DSMEM_TOTAL>>>(
                ih, WH16 + wo, WT16 + wo, WC16 + wo,
                bH + s * HID, bT + s * HID, bC + s * HID,
                ih, nullptr, oh);
    }
}

// round 17
// speedup vs baseline: 1.4645x; 1.0989x over previous
#include <cuda_runtime.h>
#include <cuda_fp16.h>
#include <cstdint>

#define HID 1024
#define MROWS 32768
#define STAGE 32768
#define DSMEM_TOTAL (2 * STAGE)

// ---- static device scratch (allocation-free rule) ----
__device__ __align__(16) __half g_x16 [(size_t)MROWS * 512];
__device__ __align__(16) __half g_w16 [(size_t)3 * HID * 512];
__device__ __align__(16) __half g_WH16[(size_t)5 * HID * HID];
__device__ __align__(16) __half g_WT16[(size_t)5 * HID * HID];
__device__ __align__(16) __half g_WC16[(size_t)5 * HID * HID];
__device__ __align__(16) __half g_h16A[(size_t)MROWS * HID];
__device__ __align__(16) __half g_h16B[(size_t)MROWS * HID];

// ---- helpers ----
__device__ __forceinline__ uint32_t smem_u32(const void* p) {
    uint32_t a;
    asm("{ .reg .u64 t; cvta.to.shared.u64 t, %1; cvt.u32.u64 %0, t; }" : "=r"(a) : "l"(p));
    return a;
}
__device__ __forceinline__ void cpa16(uint32_t s, const void* g) {
    asm volatile("cp.async.cg.shared.global [%0], [%1], 16;" :: "r"(s), "l"(g));
}
__device__ __forceinline__ void cpa_commit() {
    asm volatile("cp.async.commit_group;" ::: "memory");
}
__device__ __forceinline__ void cpa_wait1() {
    asm volatile("cp.async.wait_group 1;" ::: "memory");
}
__device__ __forceinline__ void ldsm4(uint32_t* r, uint32_t a) {
    asm volatile("ldmatrix.sync.aligned.m8n8.x4.shared.b16 {%0,%1,%2,%3}, [%4];"
                 : "=r"(r[0]), "=r"(r[1]), "=r"(r[2]), "=r"(r[3]) : "r"(a));
}
__device__ __forceinline__ void mma16816(float* d, const uint32_t* a, uint32_t b0, uint32_t b1) {
    asm volatile(
        "mma.sync.aligned.m16n8k16.row.col.f32.f16.f16.f32 "
        "{%0,%1,%2,%3}, {%4,%5,%6,%7}, {%8,%9}, {%0,%1,%2,%3};"
        : "+f"(d[0]), "+f"(d[1]), "+f"(d[2]), "+f"(d[3])
        : "r"(a[0]), "r"(a[1]), "r"(a[2]), "r"(a[3]), "r"(b0), "r"(b1));
}
// swizzled byte offset inside a k64 (128B-row) fp16 tile: row r, 16B chunk c (0..7)
__device__ __forceinline__ uint32_t swz64(int r, int c) {
    return (uint32_t)(r * 128 + ((c ^ (r & 7)) << 4));
}
__device__ __forceinline__ float sigm_(float x) { return __fdividef(1.f, 1.f + __expf(-x)); }
__device__ __forceinline__ float tanh_(float x) {
    float ax = fabsf(x), e = __expf(-2.f * ax);
    float t = __fdividef(1.f - e, 1.f + e);
    return x >= 0.f ? t : -t;
}
__device__ __forceinline__ uint32_t f2h(float f) {
    return (uint32_t)__half_as_ushort(__float2half_rn(f));
}
__device__ __forceinline__ float h2f_lo(uint32_t u) {
    return __half2float(__ushort_as_half((unsigned short)(u & 0xFFFFu)));
}
__device__ __forceinline__ float h2f_hi(uint32_t u) {
    return __half2float(__ushort_as_half((unsigned short)(u >> 16)));
}

// ---- fp32 -> fp16 convert ----
__global__ void cvt4(const float4* __restrict__ src, uint2* __restrict__ dst, int n4) {
    int i = blockIdx.x * blockDim.x + threadIdx.x;
    if (i >= n4) return;
    float4 v = src[i];
    uint2 o;
    o.x = f2h(v.x) | (f2h(v.y) << 16);
    o.y = f2h(v.z) | (f2h(v.w) << 16);
    dst[i] = o;
}
__global__ void cvt4w(const float4* __restrict__ s0, uint2* __restrict__ d0,
                      const float4* __restrict__ s1, uint2* __restrict__ d1,
                      const float4* __restrict__ s2, uint2* __restrict__ d2, int n4) {
    int i = blockIdx.x * blockDim.x + threadIdx.x;
    if (i >= n4) return;
    const float4* src = blockIdx.z == 0 ? s0 : (blockIdx.z == 1 ? s1 : s2);
    uint2* dst = blockIdx.z == 0 ? d0 : (blockIdx.z == 1 ? d1 : d2);
    float4 v = src[i];
    uint2 o;
    o.x = f2h(v.x) | (f2h(v.y) << 16);
    o.y = f2h(v.z) | (f2h(v.w) << 16);
    dst[i] = o;
}

// ---- fused 3-gate fp16 mma.sync GEMM + epilogue ----
// CTA tile M=64, N=64 per gate, 3 gates. 128 threads, 4 warps (warp = 16-col n-group,
// covers all 64 M-rows). B LDSM redundancy 1, A redundancy 4. 3 CTAs/SM.
// k64 chunks, 2-stage double buffer. smem stage: A[0,8K); Bg at 8K+g*8K.
// A-fragments software-pipelined across the 4 k16 slices.
template<int KF, int MODE, int WRH>
__global__ void __launch_bounds__(128, 3)
rhn_h(const __half* __restrict__ Ah,
      const __half* __restrict__ B0, const __half* __restrict__ B1, const __half* __restrict__ B2,
      const float* __restrict__ e0, const float* __restrict__ e1, const float* __restrict__ e2,
      const __half* __restrict__ hin,
      float* __restrict__ outF, __half* __restrict__ outH)
{
    constexpr int NK = KF / 64;
    constexpr int JSTRIDE = 16 * KF * 2;   // 16 rows in bytes
    extern __shared__ __align__(128) uint8_t smemraw[];
    const uint32_t sbase = smem_u32(smemraw);

    const int tid = threadIdx.x;
    const int lane = tid & 31;
    const int w = tid >> 5;
    const int m0 = blockIdx.y * 64;
    const int n0 = blockIdx.x * 64;

    // ---- producer mapping: 16 x cpa16 per thread per stage ----
    const int br = tid >> 3;
    const int pc = tid & 7;
    const char* gA = (const char*)(Ah + (size_t)(m0 + br) * KF + pc * 8);
    const char* gB[3];
    {
        const __half* bp[3] = {B0, B1, B2};
#pragma unroll
        for (int g = 0; g < 3; g++)
            gB[g] = (const char*)(bp[g] + (size_t)(n0 + br) * KF + pc * 8);
    }
    const uint32_t soA = swz64(br, pc);

    // ---- consumer bases ----
    const int mat = lane >> 3;
    const int khf = lane >> 4;
    const int swl = lane & 7;
    uint32_t aoffb[4];
#pragma unroll
    for (int mi = 0; mi < 4; mi++)
        aoffb[mi] = (uint32_t)((mi * 16 + (mat & 1) * 8 + swl) * 128);
    const uint32_t boffb = 8192u + (uint32_t)((w * 16 + (mat & 1) * 8 + swl) * 128);
    uint32_t cidx[4];
#pragma unroll
    for (int ks = 0; ks < 4; ks++)
        cidx[ks] = (uint32_t)(((ks * 2 + khf) ^ swl) << 4);

    float acc[3][4][2][4];
#pragma unroll
    for (int g = 0; g < 3; g++)
#pragma unroll
        for (int mi = 0; mi < 4; mi++)
#pragma unroll
            for (int nf = 0; nf < 2; nf++)
#pragma unroll
                for (int e = 0; e < 4; e++) acc[g][mi][nf][e] = 0.f;

#define ISSUE_TO(SB)                                                          \
    {                                                                         \
        _Pragma("unroll")                                                     \
        for (int j = 0; j < 4; j++) {                                         \
            cpa16((SB) + soA + j * 2048u, gA + (size_t)j * JSTRIDE);          \
            _Pragma("unroll")                                                 \
            for (int g = 0; g < 3; g++)                                       \
                cpa16((SB) + soA + 8192u + g * 8192u + j * 2048u,             \
                      gB[g] + (size_t)j * JSTRIDE);                           \
        }                                                                     \
    }
#define ADV()                                                                 \
    { gA += 128; gB[0] += 128; gB[1] += 128; gB[2] += 128; }

#define LDA(DST, KS)                                                          \
    {                                                                         \
        _Pragma("unroll")                                                     \
        for (int mi = 0; mi < 4; mi++)                                        \
            ldsm4((DST) + mi * 4, rd + aoffb[mi] + cidx[KS]);                 \
    }
#define LDB(DST, KS)                                                          \
    {                                                                         \
        uint32_t bb_ = rd + boffb + cidx[KS];                                 \
        ldsm4((DST), bb_);                                                    \
        ldsm4((DST) + 4, bb_ + 8192u);                                        \
        ldsm4((DST) + 8, bb_ + 16384u);                                       \
    }
#define MMAALL(A4, B4)                                                        \
    {                                                                         \
        _Pragma("unroll")                                                     \
        for (int g = 0; g < 3; g++)                                           \
            _Pragma("unroll")                                                 \
            for (int mi = 0; mi < 4; mi++) {                                  \
                mma16816(acc[g][mi][0], (A4) + mi * 4, (B4)[g * 4 + 0], (B4)[g * 4 + 2]); \
                mma16816(acc[g][mi][1], (A4) + mi * 4, (B4)[g * 4 + 1], (B4)[g * 4 + 3]); \
            }                                                                 \
    }

    // preload chunks 0,1 into slots 0,1
    ISSUE_TO(sbase); cpa_commit(); ADV();
    ISSUE_TO(sbase + STAGE); cpa_commit(); ADV();

    uint32_t rd = sbase;

    for (int i = 0; i < NK; i++) {
        cpa_wait1();
        __syncthreads();

        {
            uint32_t aX[16], aY[16], b4[12];
            // software-pipelined A fragments across the 4 k16 slices
            LDA(aX, 0);
            LDB(b4, 0); LDA(aY, 1); MMAALL(aX, b4);
            LDB(b4, 1); LDA(aX, 2); MMAALL(aY, b4);
            LDB(b4, 2); LDA(aY, 3); MMAALL(aX, b4);
            LDB(b4, 3);             MMAALL(aY, b4);
        }
        __syncthreads();

        if (i + 2 < NK) { ISSUE_TO(rd); ADV(); }
        cpa_commit();
        rd ^= STAGE;
    }

    // ---- epilogue ----
    float bA[2][2], bB[2][2], bC2[2][2], bD[2][2];
#pragma unroll
    for (int nf = 0; nf < 2; nf++) {
        int n = n0 + w * 16 + nf * 8 + (lane & 3) * 2;
        if (MODE == 0) {
            float2 i0 = *(const float2*)&e0[n],         h0 = *(const float2*)&e1[n];
            float2 i1 = *(const float2*)&e0[HID + n],   h1 = *(const float2*)&e1[HID + n];
            float2 i2 = *(const float2*)&e0[2*HID + n], h2 = *(const float2*)&e1[2*HID + n];
            bA[nf][0] = i0.x + h0.x; bA[nf][1] = i0.y + h0.y;
            bB[nf][0] = i1.x + h1.x; bB[nf][1] = i1.y + h1.y;
            bC2[nf][0] = i2.x;       bC2[nf][1] = i2.y;
            bD[nf][0] = h2.x;        bD[nf][1] = h2.y;
        } else {
            float2 v0 = *(const float2*)&e0[n];
            float2 v1 = *(const float2*)&e1[n];
            float2 v2 = *(const float2*)&e2[n];
            bA[nf][0] = v0.x; bA[nf][1] = v0.y;
            bB[nf][0] = v1.x; bB[nf][1] = v1.y;
            bC2[nf][0] = v2.x; bC2[nf][1] = v2.y;
        }
    }

#pragma unroll
    for (int mi = 0; mi < 4; mi++) {
#pragma unroll
        for (int half = 0; half < 2; half++) {
            const int m = m0 + mi * 16 + (lane >> 2) + half * 8;
#pragma unroll
            for (int nf = 0; nf < 2; nf++) {
                const int n = n0 + w * 16 + nf * 8 + (lane & 3) * 2;
                float res[2];
                float hv0 = 0.f, hv1 = 0.f;
                if (MODE == 1) {
                    uint32_t hw = *(const uint32_t*)(hin + (size_t)m * HID + n);
                    hv0 = h2f_lo(hw); hv1 = h2f_hi(hw);
                }
#pragma unroll
                for (int e = 0; e < 2; e++) {
                    float a0 = acc[0][mi][nf][half * 2 + e];
                    float a1 = acc[1][mi][nf][half * 2 + e];
                    float a2 = acc[2][mi][nf][half * 2 + e];
                    if (MODE == 0) {
                        float r = sigm_(a0 + bA[nf][e]);
                        float z = sigm_(a1 + bB[nf][e]);
                        float nn = tanh_(a2 + bC2[nf][e] + r * bD[nf][e]);
                        res[e] = (1.f - z) * nn;
                    } else {
                        float hh = tanh_(a0 + bA[nf][e]);
                        float t  = sigm_(a1 + bB[nf][e]);
                        float cc = sigm_(a2 + bC2[nf][e]);
                        float hi = (e == 0) ? hv0 : hv1;
                        res[e] = hh * t + hi * (1.f - cc);
                    }
                }
                if (WRH) {
                    *(uint32_t*)(outH + (size_t)m * HID + n) = f2h(res[0]) | (f2h(res[1]) << 16);
                } else {
                    *(float2*)(outF + (size_t)m * HID + n) = make_float2(res[0], res[1]);
                }
            }
        }
    }
}

extern "C" void kernel_launch(void* const* d_in, const int* in_sizes, int n_in,
                              void* d_out, int out_size)
{
    const float* x    = (const float*)d_in[0];
    const float* w_ih = (const float*)d_in[1];
    const float* b_ih = (const float*)d_in[3];
    const float* b_hh = (const float*)d_in[4];
    const float* WH   = (const float*)d_in[5];
    const float* bH   = (const float*)d_in[6];
    const float* WT   = (const float*)d_in[7];
    const float* bT   = (const float*)d_in[8];
    const float* WC   = (const float*)d_in[9];
    const float* bC   = (const float*)d_in[10];
    float* out = (float*)d_out;

    static bool attrSet = false;
    if (!attrSet) {
        cudaFuncSetAttribute(rhn_h<512, 0, 1>,  cudaFuncAttributeMaxDynamicSharedMemorySize, DSMEM_TOTAL);
        cudaFuncSetAttribute(rhn_h<1024, 1, 1>, cudaFuncAttributeMaxDynamicSharedMemorySize, DSMEM_TOTAL);
        cudaFuncSetAttribute(rhn_h<1024, 1, 0>, cudaFuncAttributeMaxDynamicSharedMemorySize, DSMEM_TOTAL);
        attrSet = true;
    }

    __half *x16, *w16, *WH16, *WT16, *WC16, *h16A, *h16B;
    cudaGetSymbolAddress((void**)&x16, g_x16);
    cudaGetSymbolAddress((void**)&w16, g_w16);
    cudaGetSymbolAddress((void**)&WH16, g_WH16);
    cudaGetSymbolAddress((void**)&WT16, g_WT16);
    cudaGetSymbolAddress((void**)&WC16, g_WC16);
    cudaGetSymbolAddress((void**)&h16A, g_h16A);
    cudaGetSymbolAddress((void**)&h16B, g_h16B);

    {
        int n4 = MROWS * 512 / 4;
        cvt4<<<(n4 + 255) / 256, 256>>>((const float4*)x, (uint2*)x16, n4);
        n4 = 3 * HID * 512 / 4;
        cvt4<<<(n4 + 255) / 256, 256>>>((const float4*)w_ih, (uint2*)w16, n4);
        n4 = 5 * HID * HID / 4;
        dim3 g((n4 + 255) / 256, 1, 3);
        cvt4w<<<g, 256>>>((const float4*)WH, (uint2*)WH16,
                          (const float4*)WT, (uint2*)WT16,
                          (const float4*)WC, (uint2*)WC16, n4);
    }

    dim3 grd(HID / 64, MROWS / 64);
    rhn_h<512, 0, 1><<<grd, 128, DSMEM_TOTAL>>>(
        x16,
        w16, w16 + (size_t)HID * 512, w16 + (size_t)2 * HID * 512,
        b_ih, b_hh, nullptr,
        nullptr, nullptr, h16A);

    for (int s = 0; s < 5; s++) {
        size_t wo = (size_t)s * HID * HID;
        const __half* ih = (s & 1) ? h16B : h16A;
        __half* oh = (s & 1) ? h16A : h16B;
        if (s == 4)
            rhn_h<1024, 1, 0><<<grd, 128, DSMEM_TOTAL>>>(
                ih, WH16 + wo, WT16 + wo, WC16 + wo,
                bH + s * HID, bT + s * HID, bC + s * HID,
                ih, out, nullptr);
        else
            rhn_h<1024, 1, 1><<<grd, 128, DSMEM_TOTAL>>>(
                ih, WH16 + wo, WT16 + wo, WC16 + wo,
                bH + s * HID, bT + s * HID, bC + s * HID,
                ih, nullptr, oh);
    }
}